// round 13
// baseline (speedup 1.0000x reference)
#include <cuda_runtime.h>
#include <cuda_fp16.h>
#include <cstdint>

// Problem dims
#define B_BATCH   128
#define T_SEQ     2048
#define K_DIM     128    // J (softmax / contraction dim)
#define N_DIM     512    // d (output feature dim)
#define M_TILE    128
#define NCHUNK    128    // N processed in 4 register chunks of 128
#define NCHUNKS   4
#define THREADS   384    // 8 consumer warps + 4 producer warps
#define CONS_THREADS 256

#define NUNITS    1024             // 2048 tiles / 2-tile units
#define GRID_MAIN 152              // persistent CTAs (1/SM)

#define A_PITCH_B 272    // bytes per A row (136 fp16; 8-half pad -> conflict-free ldsm)
#define B_PITCH_B 1040   // bytes per B row (520 fp16; 8-half pad -> conflict-free ldsm.trans)
#define A_BYTES   (128 * A_PITCH_B)     // 34,816 (x2 buffers)
#define B_BYTES   (128 * B_PITCH_B)     // 133,120
static constexpr unsigned SMEM_TOTAL = 2 * A_BYTES + B_BYTES + 16;  // 202,768

// fp16 copy of U (one-time convert): 16.7 MB as uint2 (L2-resident).
__device__ __align__(16) uint2 g_U16[(size_t)B_BATCH * K_DIM * N_DIM / 4];
__device__ unsigned g_counter;

// ---------------- helpers ----------------
static __device__ __forceinline__ uint32_t smem_u32(const void* p) {
    uint32_t a;
    asm("{ .reg .u64 t; cvta.to.shared.u64 t, %1; cvt.u32.u64 %0, t; }" : "=r"(a) : "l"(p));
    return a;
}

static __device__ __forceinline__ uint32_t pack_f16x2(float x, float y) {
    uint32_t r;
    asm("cvt.rn.f16x2.f32 %0, %1, %2;" : "=r"(r) : "f"(y), "f"(x));
    return r;
}

static __device__ __forceinline__ void cp_async16(uint32_t saddr, const void* gptr) {
    asm volatile("cp.async.cg.shared.global [%0], [%1], 16;"
                 :: "r"(saddr), "l"(gptr) : "memory");
}
static __device__ __forceinline__ void cp_commit() {
    asm volatile("cp.async.commit_group;" ::: "memory");
}
template <int N>
static __device__ __forceinline__ void cp_wait() {
    asm volatile("cp.async.wait_group %0;" :: "n"(N) : "memory");
}

static __device__ __forceinline__ void ldsm_x4(
    uint32_t& r0, uint32_t& r1, uint32_t& r2, uint32_t& r3, uint32_t addr)
{
    asm volatile("ldmatrix.sync.aligned.m8n8.x4.shared.b16 {%0,%1,%2,%3}, [%4];"
                 : "=r"(r0), "=r"(r1), "=r"(r2), "=r"(r3) : "r"(addr));
}

static __device__ __forceinline__ void ldsm_x4_trans(
    uint32_t& r0, uint32_t& r1, uint32_t& r2, uint32_t& r3, uint32_t addr)
{
    asm volatile("ldmatrix.sync.aligned.m8n8.x4.trans.shared.b16 {%0,%1,%2,%3}, [%4];"
                 : "=r"(r0), "=r"(r1), "=r"(r2), "=r"(r3) : "r"(addr));
}

static __device__ __forceinline__ void mma_f16(
    float& c0, float& c1, float& c2, float& c3,
    uint32_t a0, uint32_t a1, uint32_t a2, uint32_t a3,
    uint32_t b0, uint32_t b1)
{
    asm volatile(
        "mma.sync.aligned.m16n8k16.row.col.f32.f16.f16.f32 "
        "{%0,%1,%2,%3}, {%4,%5,%6,%7}, {%8,%9}, {%0,%1,%2,%3};"
        : "+f"(c0), "+f"(c1), "+f"(c2), "+f"(c3)
        : "r"(a0), "r"(a1), "r"(a2), "r"(a3), "r"(b0), "r"(b1));
}

// ---------------- pre-kernel: U fp32 -> fp16 scratch + counter reset ----------------
__global__ void __launch_bounds__(256)
convert_U_kernel(const float* __restrict__ U)
{
    if (blockIdx.x == 0 && threadIdx.x == 0) g_counter = 0;
    const int idx = blockIdx.x * 256 + threadIdx.x;     // one float4 per thread
    const float4 v = reinterpret_cast<const float4*>(U)[idx];
    uint2 p;
    p.x = pack_f16x2(v.x, v.y);
    p.y = pack_f16x2(v.z, v.w);
    g_U16[idx] = p;
}

// producers (128 threads): each thread copies one 1024B k-row of U16[b] via cp.async
static __device__ __forceinline__ void issue_b_fill_prod(uint32_t sB, int b, int ptid)
{
    const char* src = reinterpret_cast<const char*>(g_U16)
                    + (size_t)b * K_DIM * N_DIM * 2 + (size_t)ptid * 1024;
    const uint32_t dst = sB + (uint32_t)ptid * B_PITCH_B;
#pragma unroll
    for (int g = 0; g < 64; ++g)
        cp_async16(dst + (uint32_t)g * 16u, src + g * 16);
    cp_commit();
}

// tile m0 within batch for (unit, sub)
static __device__ __forceinline__ int unit_m0(int w, int sub) {
    return (((w & 7) << 1) | sub) * M_TILE;
}

// ---------------- main kernel ----------------
// 152 persistent CTAs, 384 threads: warps 0-7 consumers (MMA), 8-11 producers
// (softmax for next tile into alternate A buffer, work grab, B refill).
// Work unit = 2 M-tiles of one batch. U16[b] resident; A double-buffered.
__global__ void __launch_bounds__(THREADS, 1)
C2Q_15032385536516_kernel(const float* __restrict__ S,
                          float* __restrict__ Out)
{
    extern __shared__ char smem[];
    const uint32_t sA = smem_u32(smem);                 // 2 x A buffers
    const uint32_t sB = sA + 2 * A_BYTES;
    volatile int* mail = reinterpret_cast<volatile int*>(smem + 2 * A_BYTES + B_BYTES);

    const int tid  = threadIdx.x;
    const int lane = tid & 31;
    const int wid  = tid >> 5;
    const bool consumer = (wid < 8);
    const int ptid = tid - CONS_THREADS;   // producer-local id (valid when !consumer)

    // ---- consumer fragment base addresses (buffer 0; add p*A_BYTES at use) ----
    const int warpM = wid & 1;
    const int warpN = wid >> 1;
    const int l8 = lane & 7;
    const int tl = lane >> 3;
    uint32_t aAddr[4];
#pragma unroll
    for (int mf = 0; mf < 4; ++mf) {
        const int row = warpM * 64 + mf * 16 + ((tl & 1) << 3) + l8;
        aAddr[mf] = sA + (uint32_t)row * A_PITCH_B + (uint32_t)(tl >> 1) * 16u;
    }
    const uint32_t bLaneOff =
        (uint32_t)(lane & 15) * B_PITCH_B + (uint32_t)((lane >> 4) << 3) * 2u;
    const uint32_t bWarpCol = (uint32_t)(warpN * 32) * 2u;

    // ---- initial work grab ----
    if (tid == CONS_THREADS) *mail = (int)atomicAdd(&g_counter, 1u);
    __syncthreads();
    int w = *mail;
    if (w >= NUNITS) return;       // whole CTA, uniform
    int tsub = 0;
    int b  = w >> 3;
    int m0 = unit_m0(w, 0);

    // ---- startup: producers fill B(b) and A[0] = softmax(tile (b,m0)) ----
    if (!consumer) {
        issue_b_fill_prod(sB, b, ptid);
#pragma unroll 1
        for (int pass = 0; pass < 2; ++pass) {
            const int row  = pass * 64 + (ptid >> 1);
            const int half = ptid & 1;
            const float4* sp = reinterpret_cast<const float4*>(
                S + (size_t)(b * T_SEQ + m0 + row) * K_DIM + half * 64);
            float4 e[16];
            float sum = 0.f;
#pragma unroll
            for (int i = 0; i < 16; ++i) {
                float4 x = sp[i];
                e[i].x = __expf(x.x); e[i].y = __expf(x.y);
                e[i].z = __expf(x.z); e[i].w = __expf(x.w);
                sum += (e[i].x + e[i].y) + (e[i].z + e[i].w);
            }
            sum += __shfl_xor_sync(0xffffffffu, sum, 1);
            const float inv = 1.0f / sum;
            char* arow = smem + (size_t)row * A_PITCH_B + half * 128;
#pragma unroll
            for (int i = 0; i < 8; ++i) {
                uint4 t;
                t.x = pack_f16x2(e[2 * i].x * inv,     e[2 * i].y * inv);
                t.y = pack_f16x2(e[2 * i].z * inv,     e[2 * i].w * inv);
                t.z = pack_f16x2(e[2 * i + 1].x * inv, e[2 * i + 1].y * inv);
                t.w = pack_f16x2(e[2 * i + 1].z * inv, e[2 * i + 1].w * inv);
                *reinterpret_cast<uint4*>(arow + i * 16) = t;
            }
        }
        cp_wait<0>();
    }
    __syncthreads();               // A[0] + B resident for consumers
    int p = 0;
    int nw = 0;

    // ---- persistent tile loop ----
    while (true) {
        // identity of next tile
        int nuw, nusub; bool nxtValid;
        if (tsub == 0) { nuw = w;  nusub = 1; nxtValid = true; }
        else           { nuw = nw; nusub = 0; nxtValid = (nw < NUNITS); }
        const int nb  = nuw >> 3;
        const int nm0 = unit_m0(nuw, nusub);

        if (consumer) {
            // ======== mainloop(cur): 4 N-chunks over resident B ========
            float* outBase = Out + (size_t)(b * T_SEQ + m0) * N_DIM;
            const uint32_t aBuf = (uint32_t)p * A_BYTES;
#pragma unroll 1
            for (int c = 0; c < NCHUNKS; ++c) {
                const uint32_t bChunk = sB + bLaneOff + bWarpCol
                                      + (uint32_t)(c * NCHUNK) * 2u;
                float acc[4][4][4];
#pragma unroll
                for (int mf = 0; mf < 4; ++mf)
#pragma unroll
                    for (int nf = 0; nf < 4; ++nf)
#pragma unroll
                        for (int r = 0; r < 4; ++r) acc[mf][nf][r] = 0.f;

#pragma unroll
                for (int s = 0; s < 8; ++s) {
                    uint32_t a[4][4];
#pragma unroll
                    for (int mf = 0; mf < 4; ++mf)
                        ldsm_x4(a[mf][0], a[mf][1], a[mf][2], a[mf][3],
                                aAddr[mf] + aBuf + (uint32_t)s * 32u);
                    uint32_t bf[2][4];
#pragma unroll
                    for (int np = 0; np < 2; ++np)
                        ldsm_x4_trans(bf[np][0], bf[np][1], bf[np][2], bf[np][3],
                                      bChunk + (uint32_t)(np * 16) * 2u
                                             + (uint32_t)s * (16u * B_PITCH_B));
#pragma unroll
                    for (int mf = 0; mf < 4; ++mf)
#pragma unroll
                        for (int nf = 0; nf < 4; ++nf)
                            mma_f16(acc[mf][nf][0], acc[mf][nf][1],
                                    acc[mf][nf][2], acc[mf][nf][3],
                                    a[mf][0], a[mf][1], a[mf][2], a[mf][3],
                                    bf[nf >> 1][2 * (nf & 1)],
                                    bf[nf >> 1][2 * (nf & 1) + 1]);
                }

                const int colBase = c * NCHUNK + warpN * 32 + 2 * (lane & 3);
                const int rowBase = warpM * 64 + (lane >> 2);
#pragma unroll
                for (int mf = 0; mf < 4; ++mf) {
                    const int r0 = rowBase + mf * 16;
#pragma unroll
                    for (int nf = 0; nf < 4; ++nf) {
                        const int col = colBase + nf * 8;
                        float2 v0 = make_float2(acc[mf][nf][0], acc[mf][nf][1]);
                        float2 v1 = make_float2(acc[mf][nf][2], acc[mf][nf][3]);
                        __stcs(reinterpret_cast<float2*>(
                                   outBase + (size_t)r0 * N_DIM + col), v0);
                        __stcs(reinterpret_cast<float2*>(
                                   outBase + (size_t)(r0 + 8) * N_DIM + col), v1);
                    }
                }
            }
        } else {
            // ======== producers: softmax(next tile) -> A[p^1]; grab work ========
            if (nxtValid) {
#pragma unroll 1
                for (int pass = 0; pass < 2; ++pass) {
                    const int row  = pass * 64 + (ptid >> 1);
                    const int half = ptid & 1;
                    const float4* sp = reinterpret_cast<const float4*>(
                        S + (size_t)(nb * T_SEQ + nm0 + row) * K_DIM + half * 64);
                    float4 e[16];
                    float sum = 0.f;
#pragma unroll
                    for (int i = 0; i < 16; ++i) {
                        float4 x = sp[i];
                        e[i].x = __expf(x.x); e[i].y = __expf(x.y);
                        e[i].z = __expf(x.z); e[i].w = __expf(x.w);
                        sum += (e[i].x + e[i].y) + (e[i].z + e[i].w);
                    }
                    sum += __shfl_xor_sync(0xffffffffu, sum, 1);
                    const float inv = 1.0f / sum;
                    char* arow = smem + (size_t)(p ^ 1) * A_BYTES
                                      + (size_t)row * A_PITCH_B + half * 128;
#pragma unroll
                    for (int i = 0; i < 8; ++i) {
                        uint4 t;
                        t.x = pack_f16x2(e[2 * i].x * inv,     e[2 * i].y * inv);
                        t.y = pack_f16x2(e[2 * i].z * inv,     e[2 * i].w * inv);
                        t.z = pack_f16x2(e[2 * i + 1].x * inv, e[2 * i + 1].y * inv);
                        t.w = pack_f16x2(e[2 * i + 1].z * inv, e[2 * i + 1].w * inv);
                        *reinterpret_cast<uint4*>(arow + i * 16) = t;
                    }
                }
            }
            if (tsub == 0 && tid == CONS_THREADS)
                *mail = (int)atomicAdd(&g_counter, 1u);
        }

        __syncthreads();           // tile boundary: A[p^1] ready, mainloop done, mail visible
        if (tsub == 0) nw = *mail;

        if (!nxtValid) break;

        if (nb != b) {             // batch change: refill resident B (uniform branch)
            if (!consumer) {
                issue_b_fill_prod(sB, nb, ptid);
                cp_wait<0>();
            }
            __syncthreads();       // new B visible to consumers
        }

        b = nb; w = nuw; tsub = nusub; m0 = nm0; p ^= 1;
    }
}

extern "C" void kernel_launch(void* const* d_in, const int* in_sizes, int n_in,
                              void* d_out, int out_size)
{
    const float* U = (const float*)d_in[0];
    const float* S = (const float*)d_in[1];
    // Robustness: U has 8.4M elements, S has 33.5M. Swap if order differs.
    if (n_in >= 2 && in_sizes[0] == B_BATCH * T_SEQ * K_DIM) {
        const float* t = U; U = S; S = t;
    }
    float* Out = (float*)d_out;

    static int attr_set = 0;
    if (!attr_set) {
        cudaFuncSetAttribute(C2Q_15032385536516_kernel,
                             cudaFuncAttributeMaxDynamicSharedMemorySize, SMEM_TOTAL);
        attr_set = 1;
    }

    // 1) convert U fp32 -> fp16 scratch + reset work counter
    const int n_f4 = B_BATCH * K_DIM * N_DIM / 4;      // 2,097,152
    convert_U_kernel<<<n_f4 / 256, 256>>>(U);

    // 2) persistent warp-specialized fused softmax-GEMM
    C2Q_15032385536516_kernel<<<GRID_MAIN, THREADS, SMEM_TOTAL>>>(S, Out);
}

// round 14
// speedup vs baseline: 1.1270x; 1.1270x over previous
#include <cuda_runtime.h>
#include <cuda_fp16.h>
#include <cstdint>

// Problem dims
#define B_BATCH   128
#define T_SEQ     2048
#define K_DIM     128    // J (softmax / contraction dim)
#define N_DIM     512    // d (output feature dim)
#define M_TILE    64     // rows per tile (small CTA)
#define NCHUNK    128    // N streamed in 4 chunks of 128 cols
#define NCHUNKS   4
#define THREADS   128    // 4 warps, one per SMSP

#define NTILES    4096             // 32 tiles x 128 batches
#define GRID_MAIN 304              // persistent CTAs, 2/SM

#define A_PITCH_B 272    // bytes per A row (136 fp16; 8-half pad -> conflict-free ldsm)
#define B_PITCH_B 272    // bytes per B chunk row (128 data halfs + 8 pad)
#define A_BYTES   (M_TILE * A_PITCH_B)  // 17,408
#define B_BYTES   (128 * B_PITCH_B)     // 34,816 per buffer
static constexpr unsigned SMEM_TOTAL = A_BYTES + 2 * B_BYTES + 16;  // 87,056 -> 2 CTAs/SM

// fp16 copy of U (one-time convert): 16.7 MB as uint2 (L2-resident during main).
__device__ __align__(16) uint2 g_U16[(size_t)B_BATCH * K_DIM * N_DIM / 4];
__device__ unsigned g_counter;

// ---------------- helpers ----------------
static __device__ __forceinline__ uint32_t smem_u32(const void* p) {
    uint32_t a;
    asm("{ .reg .u64 t; cvta.to.shared.u64 t, %1; cvt.u32.u64 %0, t; }" : "=r"(a) : "l"(p));
    return a;
}

static __device__ __forceinline__ uint32_t pack_f16x2(float x, float y) {
    uint32_t r;
    asm("cvt.rn.f16x2.f32 %0, %1, %2;" : "=r"(r) : "f"(y), "f"(x));
    return r;
}

static __device__ __forceinline__ void cp_async16(uint32_t saddr, const void* gptr) {
    asm volatile("cp.async.cg.shared.global [%0], [%1], 16;"
                 :: "r"(saddr), "l"(gptr) : "memory");
}
static __device__ __forceinline__ void cp_commit() {
    asm volatile("cp.async.commit_group;" ::: "memory");
}
template <int N>
static __device__ __forceinline__ void cp_wait() {
    asm volatile("cp.async.wait_group %0;" :: "n"(N) : "memory");
}

static __device__ __forceinline__ void ldsm_x4(
    uint32_t& r0, uint32_t& r1, uint32_t& r2, uint32_t& r3, uint32_t addr)
{
    asm volatile("ldmatrix.sync.aligned.m8n8.x4.shared.b16 {%0,%1,%2,%3}, [%4];"
                 : "=r"(r0), "=r"(r1), "=r"(r2), "=r"(r3) : "r"(addr));
}

static __device__ __forceinline__ void ldsm_x4_trans(
    uint32_t& r0, uint32_t& r1, uint32_t& r2, uint32_t& r3, uint32_t addr)
{
    asm volatile("ldmatrix.sync.aligned.m8n8.x4.trans.shared.b16 {%0,%1,%2,%3}, [%4];"
                 : "=r"(r0), "=r"(r1), "=r"(r2), "=r"(r3) : "r"(addr));
}

static __device__ __forceinline__ void mma_f16(
    float& c0, float& c1, float& c2, float& c3,
    uint32_t a0, uint32_t a1, uint32_t a2, uint32_t a3,
    uint32_t b0, uint32_t b1)
{
    asm volatile(
        "mma.sync.aligned.m16n8k16.row.col.f32.f16.f16.f32 "
        "{%0,%1,%2,%3}, {%4,%5,%6,%7}, {%8,%9}, {%0,%1,%2,%3};"
        : "+f"(c0), "+f"(c1), "+f"(c2), "+f"(c3)
        : "r"(a0), "r"(a1), "r"(a2), "r"(a3), "r"(b0), "r"(b1));
}

// ---------------- pre-kernel: U fp32 -> fp16 scratch + counter reset ----------------
__global__ void __launch_bounds__(256)
convert_U_kernel(const float* __restrict__ U)
{
    if (blockIdx.x == 0 && threadIdx.x == 0) g_counter = 0;
    const int idx = blockIdx.x * 256 + threadIdx.x;     // one float4 per thread
    const float4 v = reinterpret_cast<const float4*>(U)[idx];
    uint2 p;
    p.x = pack_f16x2(v.x, v.y);
    p.y = pack_f16x2(v.z, v.w);
    g_U16[idx] = p;
}

// issue one 128x128 fp16 B chunk via cp.async (16 x 16B per thread, 128 threads)
static __device__ __forceinline__ void issue_b_chunk(
    uint32_t dst, const char* __restrict__ src16, int tid)
{
#pragma unroll
    for (int it = 0; it < 16; ++it) {
        const int idx = it * THREADS + tid;
        const int k   = idx >> 4;            // 0..127
        const int g   = idx & 15;            // 16B group within 256B chunk row
        cp_async16(dst + (uint32_t)k * B_PITCH_B + (uint32_t)g * 16u,
                   src16 + (size_t)k * (N_DIM * 2) + g * 16);
    }
    cp_commit();
}

// ---------------- main kernel ----------------
// 304 persistent CTAs (2/SM), 128 threads = 4 warps (one per SMSP).
// Tile = 64 rows x full N. B streamed in 4 double-buffered chunks per tile.
// Warp layout: all warps cover rows 0-63; warpN = wid (4 x 32 cols per chunk).
__global__ void __launch_bounds__(THREADS, 2)
C2Q_15032385536516_kernel(const float* __restrict__ S,
                          float* __restrict__ Out)
{
    extern __shared__ char smem[];
    const uint32_t sA = smem_u32(smem);           // A: fp16 probs [64][136]
    const uint32_t sB = sA + A_BYTES;             // B: 2 x fp16 chunk [128][136]
    volatile int* mail = reinterpret_cast<volatile int*>(smem + A_BYTES + 2 * B_BYTES);

    const int tid  = threadIdx.x;
    const int lane = tid & 31;
    const int wid  = tid >> 5;

    // ---- fragment base addresses (fixed for all tiles) ----
    const int warpN = wid;
    const int l8 = lane & 7;
    const int tl = lane >> 3;
    uint32_t aAddr[4];
#pragma unroll
    for (int mf = 0; mf < 4; ++mf) {
        const int row = mf * 16 + ((tl & 1) << 3) + l8;   // rows 0..63
        aAddr[mf] = sA + (uint32_t)row * A_PITCH_B + (uint32_t)(tl >> 1) * 16u;
    }
    const uint32_t bLaneOff =
        (uint32_t)(lane & 15) * B_PITCH_B + (uint32_t)((lane >> 4) << 3) * 2u;
    const uint32_t bWarpCol = (uint32_t)(warpN * 32) * 2u;

    // softmax addressing: 2 threads per row (64 rows, 128 threads)
    const int srow  = tid >> 1;
    const int shalf = tid & 1;

    // ---- initial work grab ----
    if (tid == 0) *mail = (int)atomicAdd(&g_counter, 1u);
    __syncthreads();
    int w = *mail;                 // tile index (grid 304 <= NTILES, always valid)

    // ---- persistent tile loop ----
    while (true) {
        const int b  = w >> 5;
        const int m0 = (w & 31) * M_TILE;
        const char* __restrict__ Ub16 =
            reinterpret_cast<const char*>(g_U16) + (size_t)b * K_DIM * N_DIM * 2;

        // issue B chunk 0 (arrives during softmax). Buffer 0's previous readers
        // (chunk-2 MMA of the prior tile) finished before the prior c==2 barrier.
        issue_b_chunk(sB, Ub16, tid);

        // grab next tile now; published by the post-softmax barrier
        if (tid == 0) *mail = (int)atomicAdd(&g_counter, 1u);

        // softmax: direct S read (16 independent LDG.128, MLP hides latency)
        uint4 arows[8];
        {
            const float4* sp = reinterpret_cast<const float4*>(
                S + (size_t)(b * T_SEQ + m0 + srow) * K_DIM + shalf * 64);
            float4 e[16];
            float sum = 0.f;
#pragma unroll
            for (int i = 0; i < 16; ++i) {
                float4 x = sp[i];
                e[i].x = __expf(x.x); e[i].y = __expf(x.y);
                e[i].z = __expf(x.z); e[i].w = __expf(x.w);
                sum += (e[i].x + e[i].y) + (e[i].z + e[i].w);
            }
            sum += __shfl_xor_sync(0xffffffffu, sum, 1);
            const float inv = 1.0f / sum;
#pragma unroll
            for (int i = 0; i < 8; ++i) {
                arows[i].x = pack_f16x2(e[2 * i].x * inv,     e[2 * i].y * inv);
                arows[i].y = pack_f16x2(e[2 * i].z * inv,     e[2 * i].w * inv);
                arows[i].z = pack_f16x2(e[2 * i + 1].x * inv, e[2 * i + 1].y * inv);
                arows[i].w = pack_f16x2(e[2 * i + 1].z * inv, e[2 * i + 1].w * inv);
            }
        }

        __syncthreads();           // prev tile's mainloop done reading A; mail visible

        // store A
        {
            char* arow = smem + (size_t)srow * A_PITCH_B + shalf * 128;
#pragma unroll
            for (int i = 0; i < 8; ++i)
                *reinterpret_cast<uint4*>(arow + i * 16) = arows[i];
        }
        const int nw = *mail;

        cp_wait<0>();              // chunk 0 landed
        __syncthreads();           // A + chunk 0 visible

        // ---- mainloop: 4 streamed chunks, double-buffered B via cp.async ----
        float* outBase = Out + (size_t)(b * T_SEQ + m0) * N_DIM;
#pragma unroll 1
        for (int c = 0; c < NCHUNKS; ++c) {
            if (c + 1 < NCHUNKS)
                issue_b_chunk(sB + (uint32_t)((c + 1) & 1) * B_BYTES,
                              Ub16 + (size_t)(c + 1) * NCHUNK * 2, tid);

            const uint32_t bBuf = sB + (uint32_t)(c & 1) * B_BYTES + bLaneOff + bWarpCol;

            float acc[4][4][4];
#pragma unroll
            for (int mf = 0; mf < 4; ++mf)
#pragma unroll
                for (int nf = 0; nf < 4; ++nf)
#pragma unroll
                    for (int r = 0; r < 4; ++r) acc[mf][nf][r] = 0.f;

#pragma unroll
            for (int s = 0; s < 8; ++s) {
                uint32_t a[4][4];
#pragma unroll
                for (int mf = 0; mf < 4; ++mf)
                    ldsm_x4(a[mf][0], a[mf][1], a[mf][2], a[mf][3],
                            aAddr[mf] + (uint32_t)s * 32u);
                uint32_t bf[2][4];
#pragma unroll
                for (int np = 0; np < 2; ++np)
                    ldsm_x4_trans(bf[np][0], bf[np][1], bf[np][2], bf[np][3],
                                  bBuf + (uint32_t)(np * 16) * 2u
                                       + (uint32_t)s * (16u * B_PITCH_B));
#pragma unroll
                for (int mf = 0; mf < 4; ++mf)
#pragma unroll
                    for (int nf = 0; nf < 4; ++nf)
                        mma_f16(acc[mf][nf][0], acc[mf][nf][1],
                                acc[mf][nf][2], acc[mf][nf][3],
                                a[mf][0], a[mf][1], a[mf][2], a[mf][3],
                                bf[nf >> 1][2 * (nf & 1)], bf[nf >> 1][2 * (nf & 1) + 1]);
            }

            // epilogue: stream accumulators to GMEM
            const int colBase = c * NCHUNK + warpN * 32 + 2 * (lane & 3);
            const int rowBase = lane >> 2;
#pragma unroll
            for (int mf = 0; mf < 4; ++mf) {
                const int r0 = rowBase + mf * 16;
#pragma unroll
                for (int nf = 0; nf < 4; ++nf) {
                    const int col = colBase + nf * 8;
                    float2 v0 = make_float2(acc[mf][nf][0], acc[mf][nf][1]);
                    float2 v1 = make_float2(acc[mf][nf][2], acc[mf][nf][3]);
                    __stcs(reinterpret_cast<float2*>(outBase + (size_t)r0 * N_DIM + col), v0);
                    __stcs(reinterpret_cast<float2*>(outBase + (size_t)(r0 + 8) * N_DIM + col), v1);
                }
            }

            if (c + 1 < NCHUNKS) {
                cp_wait<0>();
                __syncthreads();   // next buffer landed + all warps done with old one
            }
        }

        if (nw >= NTILES) break;
        w = nw;
    }
}

extern "C" void kernel_launch(void* const* d_in, const int* in_sizes, int n_in,
                              void* d_out, int out_size)
{
    const float* U = (const float*)d_in[0];
    const float* S = (const float*)d_in[1];
    // Robustness: U has 8.4M elements, S has 33.5M. Swap if order differs.
    if (n_in >= 2 && in_sizes[0] == B_BATCH * T_SEQ * K_DIM) {
        const float* t = U; U = S; S = t;
    }
    float* Out = (float*)d_out;

    static int attr_set = 0;
    if (!attr_set) {
        cudaFuncSetAttribute(C2Q_15032385536516_kernel,
                             cudaFuncAttributeMaxDynamicSharedMemorySize, SMEM_TOTAL);
        attr_set = 1;
    }

    // 1) convert U fp32 -> fp16 scratch + reset work counter
    const int n_f4 = B_BATCH * K_DIM * N_DIM / 4;      // 2,097,152
    convert_U_kernel<<<n_f4 / 256, 256>>>(U);

    // 2) persistent fused softmax-GEMM, small CTAs, 2/SM
    C2Q_15032385536516_kernel<<<GRID_MAIN, THREADS, SMEM_TOTAL>>>(S, Out);
}

// round 15
// speedup vs baseline: 1.1285x; 1.0013x over previous
#include <cuda_runtime.h>
#include <cuda_fp16.h>
#include <cstdint>

// Problem dims
#define B_BATCH   128
#define T_SEQ     2048
#define K_DIM     128    // J (softmax / contraction dim)
#define N_DIM     512    // d (output feature dim)
#define M_TILE    64     // rows per sub-tile
#define M_UNIT    128    // rows per work unit (2 sub-tiles share B chunks)
#define NCHUNK    128    // N streamed in 4 chunks of 128 cols
#define NCHUNKS   4
#define THREADS   128    // 4 warps, one per SMSP

#define NUNITS    2048             // 16 units x 128 batches
#define GRID_MAIN 304              // persistent CTAs, 2/SM

#define A_PITCH_B 272    // bytes per A row (136 fp16; 8-half pad -> conflict-free ldsm)
#define B_PITCH_B 272    // bytes per B chunk row (128 data halfs + 8 pad)
#define A_BYTES   (M_TILE * A_PITCH_B)  // 17,408 (x2 sub-tile buffers)
#define B_BYTES   (128 * B_PITCH_B)     // 34,816 per buffer
static constexpr unsigned SMEM_TOTAL = 2 * A_BYTES + 2 * B_BYTES + 16;  // 104,464 -> 2 CTAs/SM

// fp16 copy of U (one-time convert): 16.7 MB as uint2 (L2-resident during main).
__device__ __align__(16) uint2 g_U16[(size_t)B_BATCH * K_DIM * N_DIM / 4];
__device__ unsigned g_counter;

// ---------------- helpers ----------------
static __device__ __forceinline__ uint32_t smem_u32(const void* p) {
    uint32_t a;
    asm("{ .reg .u64 t; cvta.to.shared.u64 t, %1; cvt.u32.u64 %0, t; }" : "=r"(a) : "l"(p));
    return a;
}

static __device__ __forceinline__ uint32_t pack_f16x2(float x, float y) {
    uint32_t r;
    asm("cvt.rn.f16x2.f32 %0, %1, %2;" : "=r"(r) : "f"(y), "f"(x));
    return r;
}

static __device__ __forceinline__ void cp_async16(uint32_t saddr, const void* gptr) {
    asm volatile("cp.async.cg.shared.global [%0], [%1], 16;"
                 :: "r"(saddr), "l"(gptr) : "memory");
}
static __device__ __forceinline__ void cp_commit() {
    asm volatile("cp.async.commit_group;" ::: "memory");
}
template <int N>
static __device__ __forceinline__ void cp_wait() {
    asm volatile("cp.async.wait_group %0;" :: "n"(N) : "memory");
}

static __device__ __forceinline__ void ldsm_x4(
    uint32_t& r0, uint32_t& r1, uint32_t& r2, uint32_t& r3, uint32_t addr)
{
    asm volatile("ldmatrix.sync.aligned.m8n8.x4.shared.b16 {%0,%1,%2,%3}, [%4];"
                 : "=r"(r0), "=r"(r1), "=r"(r2), "=r"(r3) : "r"(addr));
}

static __device__ __forceinline__ void ldsm_x4_trans(
    uint32_t& r0, uint32_t& r1, uint32_t& r2, uint32_t& r3, uint32_t addr)
{
    asm volatile("ldmatrix.sync.aligned.m8n8.x4.trans.shared.b16 {%0,%1,%2,%3}, [%4];"
                 : "=r"(r0), "=r"(r1), "=r"(r2), "=r"(r3) : "r"(addr));
}

static __device__ __forceinline__ void mma_f16(
    float& c0, float& c1, float& c2, float& c3,
    uint32_t a0, uint32_t a1, uint32_t a2, uint32_t a3,
    uint32_t b0, uint32_t b1)
{
    asm volatile(
        "mma.sync.aligned.m16n8k16.row.col.f32.f16.f16.f32 "
        "{%0,%1,%2,%3}, {%4,%5,%6,%7}, {%8,%9}, {%0,%1,%2,%3};"
        : "+f"(c0), "+f"(c1), "+f"(c2), "+f"(c3)
        : "r"(a0), "r"(a1), "r"(a2), "r"(a3), "r"(b0), "r"(b1));
}

// ---------------- pre-kernel: U fp32 -> fp16 scratch + counter reset ----------------
__global__ void __launch_bounds__(256)
convert_U_kernel(const float* __restrict__ U)
{
    if (blockIdx.x == 0 && threadIdx.x == 0) g_counter = 0;
    const int idx = blockIdx.x * 256 + threadIdx.x;     // one float4 per thread
    const float4 v = reinterpret_cast<const float4*>(U)[idx];
    uint2 p;
    p.x = pack_f16x2(v.x, v.y);
    p.y = pack_f16x2(v.z, v.w);
    g_U16[idx] = p;
}

// issue one 128x128 fp16 B chunk via cp.async (16 x 16B per thread, 128 threads)
static __device__ __forceinline__ void issue_b_chunk(
    uint32_t dst, const char* __restrict__ src16, int tid)
{
#pragma unroll
    for (int it = 0; it < 16; ++it) {
        const int idx = it * THREADS + tid;
        const int k   = idx >> 4;            // 0..127
        const int g   = idx & 15;            // 16B group within 256B chunk row
        cp_async16(dst + (uint32_t)k * B_PITCH_B + (uint32_t)g * 16u,
                   src16 + (size_t)k * (N_DIM * 2) + g * 16);
    }
    cp_commit();
}

// softmax for one 64-row sub-tile: thread handles one half-row -> 8 packed uint4
static __device__ __forceinline__ void softmax_rows(
    const float* __restrict__ S, int b, int rowBase, int srow, int shalf, uint4* arows)
{
    const float4* sp = reinterpret_cast<const float4*>(
        S + (size_t)(b * T_SEQ + rowBase + srow) * K_DIM + shalf * 64);
    float4 e[16];
    float sum = 0.f;
#pragma unroll
    for (int i = 0; i < 16; ++i) {
        float4 x = sp[i];
        e[i].x = __expf(x.x); e[i].y = __expf(x.y);
        e[i].z = __expf(x.z); e[i].w = __expf(x.w);
        sum += (e[i].x + e[i].y) + (e[i].z + e[i].w);
    }
    sum += __shfl_xor_sync(0xffffffffu, sum, 1);
    const float inv = 1.0f / sum;
#pragma unroll
    for (int i = 0; i < 8; ++i) {
        arows[i].x = pack_f16x2(e[2 * i].x * inv,     e[2 * i].y * inv);
        arows[i].y = pack_f16x2(e[2 * i].z * inv,     e[2 * i].w * inv);
        arows[i].z = pack_f16x2(e[2 * i + 1].x * inv, e[2 * i + 1].y * inv);
        arows[i].w = pack_f16x2(e[2 * i + 1].z * inv, e[2 * i + 1].w * inv);
    }
}

// ---------------- main kernel ----------------
// 304 persistent CTAs (2/SM), 128 threads = 4 warps (one per SMSP).
// Work unit = 128 rows (2 x 64-row sub-tiles) of one batch; B chunks streamed
// ONCE per unit and consumed by both sub-tiles. A double-buffered per sub-tile.
// Warp layout: all warps cover rows 0-63 of a sub-tile; warpN = wid (4 x 32 cols).
__global__ void __launch_bounds__(THREADS, 2)
C2Q_15032385536516_kernel(const float* __restrict__ S,
                          float* __restrict__ Out)
{
    extern __shared__ char smem[];
    const uint32_t sA = smem_u32(smem);           // 2 x A: fp16 probs [64][136]
    const uint32_t sB = sA + 2 * A_BYTES;         // 2 x B chunk [128][136]
    volatile int* mail = reinterpret_cast<volatile int*>(smem + 2 * A_BYTES + 2 * B_BYTES);

    const int tid  = threadIdx.x;
    const int lane = tid & 31;
    const int wid  = tid >> 5;

    // ---- fragment base addresses (fixed for all tiles) ----
    const int warpN = wid;
    const int l8 = lane & 7;
    const int tl = lane >> 3;
    uint32_t aAddr[4];
#pragma unroll
    for (int mf = 0; mf < 4; ++mf) {
        const int row = mf * 16 + ((tl & 1) << 3) + l8;   // rows 0..63
        aAddr[mf] = sA + (uint32_t)row * A_PITCH_B + (uint32_t)(tl >> 1) * 16u;
    }
    const uint32_t bLaneOff =
        (uint32_t)(lane & 15) * B_PITCH_B + (uint32_t)((lane >> 4) << 3) * 2u;
    const uint32_t bWarpCol = (uint32_t)(warpN * 32) * 2u;

    // softmax addressing: 2 threads per row (64 rows, 128 threads)
    const int srow  = tid >> 1;
    const int shalf = tid & 1;

    // ---- initial work grab ----
    if (tid == 0) *mail = (int)atomicAdd(&g_counter, 1u);
    __syncthreads();
    int w = *mail;                 // unit index (grid 304 <= NUNITS, always valid)

    // ---- persistent unit loop ----
    while (true) {
        const int b  = w >> 4;
        const int m0 = (w & 15) * M_UNIT;
        const char* __restrict__ Ub16 =
            reinterpret_cast<const char*>(g_U16) + (size_t)b * K_DIM * N_DIM * 2;

        // issue B chunk 0 (arrives during softmax). Buffer 0's previous readers
        // (chunk-2 MMAs of the prior unit) finished before the prior c==2 barrier.
        issue_b_chunk(sB, Ub16, tid);

        // grab next unit now; published by the post-softmax barrier
        if (tid == 0) *mail = (int)atomicAdd(&g_counter, 1u);

        // softmax both sub-tiles into registers
        uint4 arows0[8], arows1[8];
        softmax_rows(S, b, m0,          srow, shalf, arows0);
        softmax_rows(S, b, m0 + M_TILE, srow, shalf, arows1);

        __syncthreads();           // prev unit's mainloop done reading A; mail visible

        // store A0, A1
        {
            char* arow = smem + (size_t)srow * A_PITCH_B + shalf * 128;
#pragma unroll
            for (int i = 0; i < 8; ++i)
                *reinterpret_cast<uint4*>(arow + i * 16) = arows0[i];
            arow += A_BYTES;
#pragma unroll
            for (int i = 0; i < 8; ++i)
                *reinterpret_cast<uint4*>(arow + i * 16) = arows1[i];
        }
        const int nw = *mail;

        cp_wait<0>();              // chunk 0 landed
        __syncthreads();           // A + chunk 0 visible

        // ---- mainloop: 4 streamed chunks, each consumed by BOTH sub-tiles ----
        float* outBase = Out + (size_t)(b * T_SEQ + m0) * N_DIM;
#pragma unroll 1
        for (int c = 0; c < NCHUNKS; ++c) {
            if (c + 1 < NCHUNKS)
                issue_b_chunk(sB + (uint32_t)((c + 1) & 1) * B_BYTES,
                              Ub16 + (size_t)(c + 1) * NCHUNK * 2, tid);

            const uint32_t bBuf = sB + (uint32_t)(c & 1) * B_BYTES + bLaneOff + bWarpCol;

#pragma unroll
            for (int t = 0; t < 2; ++t) {
                const uint32_t aBuf = (uint32_t)t * A_BYTES;
                float acc[4][4][4];
#pragma unroll
                for (int mf = 0; mf < 4; ++mf)
#pragma unroll
                    for (int nf = 0; nf < 4; ++nf)
#pragma unroll
                        for (int r = 0; r < 4; ++r) acc[mf][nf][r] = 0.f;

#pragma unroll
                for (int s = 0; s < 8; ++s) {
                    uint32_t a[4][4];
#pragma unroll
                    for (int mf = 0; mf < 4; ++mf)
                        ldsm_x4(a[mf][0], a[mf][1], a[mf][2], a[mf][3],
                                aAddr[mf] + aBuf + (uint32_t)s * 32u);
                    uint32_t bf[2][4];
#pragma unroll
                    for (int np = 0; np < 2; ++np)
                        ldsm_x4_trans(bf[np][0], bf[np][1], bf[np][2], bf[np][3],
                                      bBuf + (uint32_t)(np * 16) * 2u
                                           + (uint32_t)s * (16u * B_PITCH_B));
#pragma unroll
                    for (int mf = 0; mf < 4; ++mf)
#pragma unroll
                        for (int nf = 0; nf < 4; ++nf)
                            mma_f16(acc[mf][nf][0], acc[mf][nf][1],
                                    acc[mf][nf][2], acc[mf][nf][3],
                                    a[mf][0], a[mf][1], a[mf][2], a[mf][3],
                                    bf[nf >> 1][2 * (nf & 1)],
                                    bf[nf >> 1][2 * (nf & 1) + 1]);
                }

                // epilogue: stream accumulators to GMEM
                const int colBase = c * NCHUNK + warpN * 32 + 2 * (lane & 3);
                const int rowBase = t * M_TILE + (lane >> 2);
#pragma unroll
                for (int mf = 0; mf < 4; ++mf) {
                    const int r0 = rowBase + mf * 16;
#pragma unroll
                    for (int nf = 0; nf < 4; ++nf) {
                        const int col = colBase + nf * 8;
                        float2 v0 = make_float2(acc[mf][nf][0], acc[mf][nf][1]);
                        float2 v1 = make_float2(acc[mf][nf][2], acc[mf][nf][3]);
                        __stcs(reinterpret_cast<float2*>(
                                   outBase + (size_t)r0 * N_DIM + col), v0);
                        __stcs(reinterpret_cast<float2*>(
                                   outBase + (size_t)(r0 + 8) * N_DIM + col), v1);
                    }
                }
            }

            if (c + 1 < NCHUNKS) {
                cp_wait<0>();
                __syncthreads();   // next buffer landed + all warps done with old one
            }
        }

        if (nw >= NUNITS) break;
        w = nw;
    }
}

extern "C" void kernel_launch(void* const* d_in, const int* in_sizes, int n_in,
                              void* d_out, int out_size)
{
    const float* U = (const float*)d_in[0];
    const float* S = (const float*)d_in[1];
    // Robustness: U has 8.4M elements, S has 33.5M. Swap if order differs.
    if (n_in >= 2 && in_sizes[0] == B_BATCH * T_SEQ * K_DIM) {
        const float* t = U; U = S; S = t;
    }
    float* Out = (float*)d_out;

    static int attr_set = 0;
    if (!attr_set) {
        cudaFuncSetAttribute(C2Q_15032385536516_kernel,
                             cudaFuncAttributeMaxDynamicSharedMemorySize, SMEM_TOTAL);
        attr_set = 1;
    }

    // 1) convert U fp32 -> fp16 scratch + reset work counter
    const int n_f4 = B_BATCH * K_DIM * N_DIM / 4;      // 2,097,152
    convert_U_kernel<<<n_f4 / 256, 256>>>(U);

    // 2) persistent fused softmax-GEMM, small CTAs, 2/SM, B shared across 2 sub-tiles
    C2Q_15032385536516_kernel<<<GRID_MAIN, THREADS, SMEM_TOTAL>>>(S, Out);
}